// round 3
// baseline (speedup 1.0000x reference)
#include <cuda_runtime.h>
#include <math.h>

#define BN 4
#define HW 25600
#define Wd 160
#define PRE_K 2048
#define TOPK 500

#define OFF_MASK (BN*HW)                 /* 102400 */
#define OFF_BOX  (OFF_MASK + BN*4*HW)    /* 512000 */
#define OFF_VAL  (OFF_BOX + BN*TOPK*4)   /* 520000 */

// ---------------- scratch (device globals; no allocation) ----------------
__device__ float               d_score[BN][HW];
__device__ float4              d_boxes4[BN][HW];
__device__ unsigned long long  d_vkey[BN][HW];
__device__ int                 d_V[BN];
__device__ int                 d_Vc[BN];
__device__ int                 d_pad[BN][PRE_K];
__device__ float               d_cscore[BN][PRE_K];
__device__ float4              d_cbox[BN][PRE_K];
__device__ unsigned long long  d_mask[BN][PRE_K][32];
__device__ unsigned long long  d_keep[BN][32];
__device__ int                 d_Nk[BN];
__device__ float4              d_hp4[BN][TOPK];
__device__ float               d_hlnp[BN][TOPK];

// ---------------- K1: per-pixel softmax score + box construction ----------------
__global__ void k1_score(const float* __restrict__ mask, const float* __restrict__ bias)
{
    int idx = blockIdx.x * blockDim.x + threadIdx.x;
    if (idx >= BN * HW) return;
    int b = idx / HW, p = idx - b * HW;
    const float* mk = mask + (size_t)b * 4 * HW;
    float x0 = mk[p], x1 = mk[HW + p], x2 = mk[2*HW + p], x3 = mk[3*HW + p];
    float mm = x0; int cl = 0;
    if (x1 > mm) { mm = x1; cl = 1; }
    if (x2 > mm) { mm = x2; cl = 2; }
    if (x3 > mm) { mm = x3; cl = 3; }
    // double-precision sum-of-exp so the float prob is the correctly rounded value
    double s = exp((double)x0 - (double)mm) + exp((double)x1 - (double)mm)
             + exp((double)x2 - (double)mm) + exp((double)x3 - (double)mm);
    float prob = (float)(1.0 / s);
    bool fr = (cl != 0) && (prob > 0.75f);
    d_score[b][p] = fr ? prob : -1.0f;

    const float* bi = bias + (size_t)b * 4 * HW;
    float y = (float)(p / Wd), x = (float)(p % Wd);
    d_boxes4[b][p] = make_float4(y + bi[p], x + bi[HW + p], y + bi[2*HW + p], x + bi[3*HW + p]);
}

// ---------------- K2: order-preserving compaction (valid keys + invalid padding) ----------------
__global__ void k2_compact()
{
    int b = blockIdx.x;
    int tid = threadIdx.x;             // 1024 threads
    int lane = tid & 31, wid = tid >> 5;
    __shared__ int sV[32], sI[32];
    __shared__ int sTotV, sTotI;
    __shared__ int runV, runI;
    if (tid == 0) { runV = 0; runI = 0; }
    __syncthreads();
    for (int c = 0; c < HW / 1024; c++) {
        int p = c * 1024 + tid;
        float sc = d_score[b][p];
        bool fv = sc > 0.0f;
        unsigned bal = __ballot_sync(0xffffffffu, fv);
        int pv = __popc(bal & ((1u << lane) - 1u));
        int tv = __popc(bal);
        if (lane == 0) { sV[wid] = tv; sI[wid] = 32 - tv; }
        __syncthreads();
        if (wid == 0) {
            int v = sV[lane], iv = sI[lane];
            int incV = v, incI = iv;
            for (int off = 1; off < 32; off <<= 1) {
                int tV = __shfl_up_sync(0xffffffffu, incV, off);
                int tI = __shfl_up_sync(0xffffffffu, incI, off);
                if (lane >= off) { incV += tV; incI += tI; }
            }
            sV[lane] = incV - v; sI[lane] = incI - iv;
            if (lane == 31) { sTotV = incV; sTotI = incI; }
        }
        __syncthreads();
        int posV = runV + sV[wid] + pv;
        int posI = runI + sI[wid] + (lane - pv);
        if (fv) {
            unsigned kb = 0xFFFFFFFFu - __float_as_uint(sc); // score>0 -> bits monotone
            d_vkey[b][posV] = (((unsigned long long)kb) << 32) | (unsigned)p;
        } else if (posI < PRE_K) {
            d_pad[b][posI] = p;
        }
        __syncthreads();
        if (tid == 0) { runV += sTotV; runI += sTotI; }
        __syncthreads();
    }
    if (tid == 0) { d_V[b] = runV; d_Vc[b] = runV < PRE_K ? runV : PRE_K; }
}

// ---------------- K3: O(V^2) rank sort of valid candidates ----------------
__global__ void k3_rank()
{
    int b = blockIdx.y;
    int t = blockIdx.x * blockDim.x + threadIdx.x;
    int V = d_V[b];
    if (t >= V) return;
    unsigned long long my = d_vkey[b][t];
    int r = 0;
    for (int j = 0; j < V; j++) r += (d_vkey[b][j] < my) ? 1 : 0;
    if (r < PRE_K) {
        int p = (int)(my & 0xffffffffu);
        float sc = __uint_as_float(0xFFFFFFFFu - (unsigned)(my >> 32));
        d_cscore[b][r] = sc;
        d_cbox[b][r]   = d_boxes4[b][p];
    }
}

// ---------------- K4: fill padding slots with lowest-index invalid pixels ----------------
__global__ void k4_pad()
{
    int b = blockIdx.y;
    int slot = blockIdx.x * blockDim.x + threadIdx.x;
    if (slot >= PRE_K) return;
    int Vc = d_Vc[b];
    if (slot >= Vc) {
        int p = d_pad[b][slot - Vc];
        d_cscore[b][slot] = -1.0f;
        d_cbox[b][slot]   = d_boxes4[b][p];
    }
}

// ---------------- K5: suppression bit-mask matrix (rows i<Vc, bits j>i, j<Vc) ----------------
__global__ void k5_iou()
{
    int b = blockIdx.y, i = blockIdx.x;
    int Vc = d_Vc[b];
    if (i >= Vc) return;
    int w = threadIdx.x;              // 32 threads: word w covers j in [w*64, w*64+64)
    float4 a = d_cbox[b][i];
    float areaA = (a.z - a.x) * (a.w - a.y);
    unsigned long long bits = 0;
    int j0 = w << 6;
    int ks = i + 1 - j0; if (ks < 0) ks = 0;
    int ke = Vc - j0;    if (ke > 64) ke = 64;
    for (int k = ks; k < ke; k++) {
        float4 c = d_cbox[b][j0 + k];
        float areaB = (c.z - c.x) * (c.w - c.y);
        float lty = fmaxf(a.x, c.x), ltx = fmaxf(a.y, c.y);
        float rby = fminf(a.z, c.z), rbx = fminf(a.w, c.w);
        float wy = fmaxf(rby - lty, 0.0f), wx = fmaxf(rbx - ltx, 0.0f);
        float inter = wy * wx;
        float iou = inter / (areaA + areaB - inter);  // exact division: matches ref semantics
        if (iou > 0.5f) bits |= 1ull << k;
    }
    d_mask[b][i][w] = bits;
}

// ---------------- K6: greedy NMS; warp0 owns keep mask, warps1-7 prefetch groups ----------------
__global__ void k6_nms()
{
    int b = blockIdx.x;
    int tid = threadIdx.x;            // 256 threads
    __shared__ unsigned long long buf[2][64 * 32];
    int Vc = d_Vc[b];
    int nG = (Vc + 63) >> 6;
    const unsigned long long* mrow = &d_mask[b][0][0];
    if (nG > 0) {
        for (int q = tid; q < 2048; q += 256) buf[0][q] = mrow[q];
    }
    __syncthreads();
    unsigned long long keepReg = 0;
    if (tid < 32) {
        int lo = tid * 64;
        int hi = Vc - lo;
        if (hi >= 64) keepReg = ~0ull;
        else if (hi > 0) keepReg = (1ull << hi) - 1ull;
    }
    for (int g = 0; g < nG; g++) {
        int par = g & 1;
        if (tid >= 32 && g + 1 < nG) {
            const unsigned long long* src = mrow + (size_t)(g + 1) * 64 * 32;
            for (int q = tid - 32; q < 2048; q += 224) buf[par ^ 1][q] = src[q];
        }
        if (tid < 32) {
            unsigned long long kwv = __shfl_sync(0xffffffffu, keepReg, g);
            int lim = Vc - (g << 6); if (lim > 64) lim = 64;
            for (int k = 0; k < lim; k++) {
                if ((kwv >> k) & 1ull) {                    // kwv uniform across lanes
                    keepReg &= ~buf[par][(k << 5) + tid];
                    kwv     &= ~buf[par][(k << 5) + g];     // in-group updates
                }
            }
        }
        __syncthreads();
    }
    if (tid < 32) d_keep[b][tid] = keepReg;
}

// ---------------- K7: stable partition by keep flag == top_k(kept_s, 500) ----------------
__global__ void k7_select(float* __restrict__ out)
{
    int b = blockIdx.x;
    int tid = threadIdx.x;            // 256 threads
    __shared__ unsigned long long kw[32];
    __shared__ int wpref[33];
    if (tid < 32) kw[tid] = d_keep[b][tid];
    __syncthreads();
    if (tid == 0) {
        int run = 0;
        for (int w = 0; w < 32; w++) { wpref[w] = run; run += __popcll(kw[w]); }
        wpref[32] = run;
        d_Nk[b] = run < TOPK ? run : TOPK;
    }
    __syncthreads();
    int keptTotal = wpref[32];
    for (int slot = tid; slot < PRE_K; slot += blockDim.x) {
        int w = slot >> 6, bo = slot & 63;
        unsigned long long word = kw[w];
        int bit = (int)((word >> bo) & 1ull);
        int kb = wpref[w] + __popcll(word & ((1ull << bo) - 1ull));
        int r = bit ? kb : keptTotal + (slot - kb);
        if (r < TOPK) {
            float4 bx = d_cbox[b][slot];
            ((float4*)(out + OFF_BOX))[b * TOPK + r] = bx;
            out[OFF_VAL + b * TOPK + r] = bit ? 1.0f : 0.0f;
            if (bit) {
                float sc = d_cscore[b][slot];
                float sy = bx.z - bx.x, sx = bx.w - bx.y;
                d_hp4[b][r] = make_float4((bx.x + bx.z) * 0.5f, (bx.y + bx.w) * 0.5f,
                                          10.0f / sy, 10.0f / sx);
                d_hlnp[b][r] = logf(sc);
            }
        }
    }
}

// ---------------- K8: heatmap, log-domain max -> single expf per pixel ----------------
__global__ void k8_heat(float* __restrict__ out)
{
    int b = blockIdx.y;
    int pix = blockIdx.x * blockDim.x + threadIdx.x;
    __shared__ float4 sh4[TOPK];
    __shared__ float  sl[TOPK];
    int Nk = d_Nk[b];
    for (int i = threadIdx.x; i < Nk; i += blockDim.x) { sh4[i] = d_hp4[b][i]; sl[i] = d_hlnp[b][i]; }
    __syncthreads();
    float fy = (float)(pix / Wd), fx = (float)(pix % Wd);
    float m = -1e30f;
    #pragma unroll 4
    for (int k = 0; k < Nk; k++) {
        float4 h = sh4[k];
        float zy = (fy - h.x) * h.z;
        float zx = (fx - h.y) * h.w;
        float e = fmaf(zy, zy, zx * zx);
        m = fmaxf(m, fmaf(-0.5f, e, sl[k]));
    }
    out[b * HW + pix] = expf(m);   // Nk==0 -> expf(-1e30) == 0
}

// ---------------- launch ----------------
extern "C" void kernel_launch(void* const* d_in, const int* in_sizes, int n_in,
                              void* d_out, int out_size)
{
    const float* mask = (const float*)d_in[0];
    const float* bias = (const float*)d_in[1];
    float* out = (float*)d_out;

    // mask pass-through output
    cudaMemcpyAsync(out + OFF_MASK, mask, (size_t)BN * 4 * HW * sizeof(float),
                    cudaMemcpyDeviceToDevice, 0);

    k1_score<<<(BN * HW + 255) / 256, 256>>>(mask, bias);
    k2_compact<<<BN, 1024>>>();
    { dim3 g(100, BN);        k3_rank<<<g, 256>>>(); }
    { dim3 g(PRE_K / 256, BN); k4_pad<<<g, 256>>>(); }
    { dim3 g(PRE_K, BN);      k5_iou<<<g, 32>>>(); }
    k6_nms<<<BN, 256>>>();
    k7_select<<<BN, 256>>>(out);
    { dim3 g(HW / 256, BN);   k8_heat<<<g, 256>>>(out); }
}

// round 4
// speedup vs baseline: 1.1490x; 1.1490x over previous
#include <cuda_runtime.h>
#include <math.h>

#define BN 4
#define HW 25600
#define Wd 160
#define PRE_K 2048
#define TOPK 500
#define NT1 1024

#define OFF_MASK (BN*HW)                 /* 102400 */
#define OFF_BOX  (OFF_MASK + BN*4*HW)    /* 512000 */
#define OFF_VAL  (OFF_BOX + BN*TOPK*4)   /* 520000 */

// ---------------- scratch (device globals; no allocation) ----------------
__device__ float               d_score[BN][HW];
__device__ float4              d_boxes4[BN][HW];
__device__ unsigned long long  d_vkey[BN][HW];      // fallback path only
__device__ float               d_cscore[BN][PRE_K];
__device__ float4              d_cbox[BN][PRE_K];
__device__ unsigned long long  d_mask[BN][PRE_K][32];
__device__ int                 d_Vc[BN];
__device__ int                 d_Nk[BN];
__device__ float4              d_hp4[BN][TOPK];
__device__ float               d_hlnp[BN][TOPK];

// ---------------- K1: per-pixel softmax score + box construction (float4) ----------------
__global__ void __launch_bounds__(256) k1_score(const float* __restrict__ mask,
                                                const float* __restrict__ bias)
{
    int idx = blockIdx.x * 256 + threadIdx.x;       // one thread = 4 consecutive pixels
    if (idx >= BN * (HW / 4)) return;
    int b = idx / (HW / 4), q = idx - b * (HW / 4);
    int p = q * 4;
    const int q4 = HW / 4;
    const float4* mk = (const float4*)(mask + (size_t)b * 4 * HW);
    const float4* bi = (const float4*)(bias + (size_t)b * 4 * HW);
    float4 m0 = mk[q], m1 = mk[q4 + q], m2 = mk[2*q4 + q], m3 = mk[3*q4 + q];
    float4 g0 = bi[q], g1 = bi[q4 + q], g2 = bi[2*q4 + q], g3 = bi[3*q4 + q];
    float c0[4] = {m0.x, m0.y, m0.z, m0.w};
    float c1[4] = {m1.x, m1.y, m1.z, m1.w};
    float c2[4] = {m2.x, m2.y, m2.z, m2.w};
    float c3[4] = {m3.x, m3.y, m3.z, m3.w};
    float h0[4] = {g0.x, g0.y, g0.z, g0.w};
    float h1[4] = {g1.x, g1.y, g1.z, g1.w};
    float h2[4] = {g2.x, g2.y, g2.z, g2.w};
    float h3[4] = {g3.x, g3.y, g3.z, g3.w};
    float y = (float)(p / Wd);                       // 160%4==0 -> same row for all 4
    float xb = (float)(p % Wd);
    float sout[4];
    #pragma unroll
    for (int u = 0; u < 4; u++) {
        float x0 = c0[u], x1 = c1[u], x2 = c2[u], x3 = c3[u];
        float mm = x0; int cl = 0;
        if (x1 > mm) { mm = x1; cl = 1; }
        if (x2 > mm) { mm = x2; cl = 2; }
        if (x3 > mm) { mm = x3; cl = 3; }
        double s = exp((double)x0 - (double)mm) + exp((double)x1 - (double)mm)
                 + exp((double)x2 - (double)mm) + exp((double)x3 - (double)mm);
        float prob = (float)(1.0 / s);
        bool fr = (cl != 0) && (prob > 0.75f);
        sout[u] = fr ? prob : -1.0f;
        float xx = xb + (float)u;
        d_boxes4[b][p + u] = make_float4(y + h0[u], xx + h1[u], y + h2[u], xx + h3[u]);
    }
    ((float4*)&d_score[b][0])[q] = make_float4(sout[0], sout[1], sout[2], sout[3]);
}

// ---------------- KB1: compact + bitonic top-2048 sort + padding (per image) ----------------
__global__ void __launch_bounds__(NT1) kb1_sort()
{
    __shared__ unsigned long long skey[PRE_K];      // 16 KB
    __shared__ int spad[PRE_K];                     // 8 KB
    __shared__ int sprefV[800];
    __shared__ int swsum[32];
    __shared__ int sTot;
    int b = blockIdx.x;
    int t = threadIdx.x, lane = t & 31, w = t >> 5;

    // phase 1: load all 25 scores per thread up-front; per (chunk,warp) valid counts
    unsigned flags = 0;
    unsigned kb[25];
    #pragma unroll
    for (int c = 0; c < 25; c++) {
        float sc = d_score[b][c * NT1 + t];
        bool fv = sc > 0.0f;
        kb[c] = ~__float_as_uint(sc);               // score>0: inverted bits, ascending = score desc
        flags |= (fv ? 1u : 0u) << c;
        unsigned bal = __ballot_sync(0xffffffffu, fv);
        if (lane == 0) sprefV[c * 32 + w] = __popc(bal);
    }
    __syncthreads();

    // phase 2: one exclusive block scan over the 800 (chunk-major) counts
    int cnt = (t < 800) ? sprefV[t] : 0;
    int inc = cnt;
    #pragma unroll
    for (int off = 1; off < 32; off <<= 1) {
        int u = __shfl_up_sync(0xffffffffu, inc, off);
        if (lane >= off) inc += u;
    }
    if (lane == 31) swsum[w] = inc;
    __syncthreads();
    if (w == 0) {
        int v2 = swsum[lane], i2 = v2;
        #pragma unroll
        for (int off = 1; off < 32; off <<= 1) {
            int u = __shfl_up_sync(0xffffffffu, i2, off);
            if (lane >= off) i2 += u;
        }
        swsum[lane] = i2 - v2;
        if (lane == 31) sTot = i2;
    }
    __syncthreads();
    int excl = swsum[w] + inc - cnt;
    if (t < 800) sprefV[t] = excl;
    __syncthreads();
    int V  = sTot;
    int Vc = V < PRE_K ? V : PRE_K;

    // phase 3: scatter keys (pixel order preserved via prefix) + padding pixel list
    #pragma unroll
    for (int c = 0; c < 25; c++) {
        bool fv = (flags >> c) & 1u;
        unsigned bal = __ballot_sync(0xffffffffu, fv);
        int pvL = __popc(bal & ((1u << lane) - 1u));
        int e  = c * 32 + w;
        int pe = sprefV[e];
        int p  = c * NT1 + t;
        if (fv) {
            int posV = pe + pvL;
            unsigned long long key = (((unsigned long long)kb[c]) << 32) | (unsigned)p;
            if (V <= PRE_K) skey[posV] = key;
            else            d_vkey[b][posV] = key;
        } else {
            int posI = (e << 5) - pe + (lane - pvL);   // exclusive invalid prefix
            if (posI < PRE_K) spad[posI] = p;
        }
    }
    __syncthreads();

    if (V <= PRE_K) {
        // bitonic sort over pow2(V) keys in shared (stable via pixel-index tiebreak in key)
        int P = 1; while (P < V) P <<= 1;
        for (int s = V + t; s < P; s += NT1) skey[s] = ~0ull;
        __syncthreads();
        for (unsigned ksz = 2; ksz <= (unsigned)P; ksz <<= 1) {
            for (unsigned j = ksz >> 1; j; j >>= 1) {
                unsigned tt = (unsigned)t;
                if (tt < (unsigned)(P >> 1)) {
                    unsigned i  = ((tt & ~(j - 1)) << 1) | (tt & (j - 1));
                    unsigned pr = i | j;
                    bool asc = (i & ksz) == 0;
                    unsigned long long a = skey[i], cc = skey[pr];
                    if ((a > cc) == asc) { skey[i] = cc; skey[pr] = a; }
                }
                __syncthreads();
            }
        }
        // emit sorted candidates + padding
        for (int s = t; s < PRE_K; s += NT1) {
            int p; float sc_;
            if (s < Vc) {
                unsigned long long k = skey[s];
                p   = (int)(k & 0xffffffffu);
                sc_ = __uint_as_float(~(unsigned)(k >> 32));
            } else {
                p   = spad[s - Vc];
                sc_ = -1.0f;
            }
            d_cscore[b][s] = sc_;
            d_cbox[b][s]   = d_boxes4[b][p];
        }
    } else {
        // fallback (V > 2048, not expected): count-rank, rounds keep barriers uniform
        int nR = (V + NT1 - 1) / NT1;
        for (int r0 = 0; r0 < nR; r0++) {
            int e = r0 * NT1 + t;
            unsigned long long ke = (e < V) ? d_vkey[b][e] : 0ull;
            int rk = 0;
            for (int base = 0; base < V; base += PRE_K) {
                int n = V - base; if (n > PRE_K) n = PRE_K;
                __syncthreads();
                for (int qq = t; qq < n; qq += NT1) skey[qq] = d_vkey[b][base + qq];
                __syncthreads();
                if (e < V) for (int j = 0; j < n; j++) rk += (skey[j] < ke) ? 1 : 0;
            }
            __syncthreads();
            if (e < V && rk < PRE_K) {
                int p = (int)(ke & 0xffffffffu);
                d_cscore[b][rk] = __uint_as_float(~(unsigned)(ke >> 32));
                d_cbox[b][rk]   = d_boxes4[b][p];
            }
        }
    }
    if (t == 0) d_Vc[b] = Vc;
}

// ---------------- K5: suppression bit-mask matrix, 8 rows/block, cbox in shared ----------------
__global__ void __launch_bounds__(256) k5_iou()
{
    __shared__ float4 scbox[PRE_K];                 // 32 KB
    int b = blockIdx.y;
    int Vc = d_Vc[b];
    int i0 = blockIdx.x * 8;
    if (i0 >= Vc) return;
    int tid = threadIdx.x;
    for (int q = tid; q < Vc; q += 256) scbox[q] = d_cbox[b][q];
    __syncthreads();
    int r = tid >> 5, lane = tid & 31;
    int i = i0 + r;
    if (i >= Vc) return;
    float4 a = scbox[i];
    float areaA = (a.z - a.x) * (a.w - a.y);
    unsigned long long bits = 0;
    int j0 = lane << 6;
    int ks = i + 1 - j0; if (ks < 0) ks = 0;
    int ke = Vc - j0;    if (ke > 64) ke = 64;
    for (int k = ks; k < ke; k++) {
        float4 c = scbox[j0 + k];
        float areaB = (c.z - c.x) * (c.w - c.y);
        float lty = fmaxf(a.x, c.x), ltx = fmaxf(a.y, c.y);
        float rby = fminf(a.z, c.z), rbx = fminf(a.w, c.w);
        float wy = fmaxf(rby - lty, 0.0f), wx = fmaxf(rbx - ltx, 0.0f);
        float inter = wy * wx;
        float iou = inter / (areaA + areaB - inter);  // IEEE div: bit-matches reference decision
        if (iou > 0.5f) bits |= 1ull << k;
    }
    d_mask[b][i][lane] = bits;
}

// ---------------- KB2: greedy bit-serial NMS + stable-partition select ----------------
__global__ void __launch_bounds__(256) kb2_nms_select(float* __restrict__ out)
{
    __shared__ unsigned long long buf[2][64 * 32];  // 32 KB double buffer
    __shared__ unsigned long long skw[32];
    __shared__ int wpref[33];
    int b = blockIdx.x;
    int tid = threadIdx.x;
    int Vc = d_Vc[b];
    int nG = (Vc + 63) >> 6;
    const unsigned long long* mrow = &d_mask[b][0][0];
    if (nG > 0) {
        for (int q = tid; q < 2048; q += 256) buf[0][q] = mrow[q];
    }
    __syncthreads();
    unsigned long long keepReg = 0;
    if (tid < 32) {
        int hi = Vc - tid * 64;
        if (hi >= 64) keepReg = ~0ull;
        else if (hi > 0) keepReg = (1ull << hi) - 1ull;
    }
    for (int g = 0; g < nG; g++) {
        int par = g & 1;
        if (tid >= 32 && g + 1 < nG) {
            const unsigned long long* src = mrow + (size_t)(g + 1) * 64 * 32;
            for (int q = tid - 32; q < 2048; q += 224) buf[par ^ 1][q] = src[q];
        }
        if (tid < 32) {
            unsigned long long kwv = __shfl_sync(0xffffffffu, keepReg, g);
            int lim = Vc - (g << 6); if (lim > 64) lim = 64;
            for (int k = 0; k < lim; k++) {
                if ((kwv >> k) & 1ull) {
                    keepReg &= ~buf[par][(k << 5) + tid];
                    kwv     &= ~buf[par][(k << 5) + g];
                }
            }
        }
        __syncthreads();
    }
    if (tid < 32) skw[tid] = keepReg;
    __syncthreads();
    if (tid == 0) {
        int run = 0;
        for (int w = 0; w < 32; w++) { wpref[w] = run; run += __popcll(skw[w]); }
        wpref[32] = run;
        d_Nk[b] = run < TOPK ? run : TOPK;
    }
    __syncthreads();
    int keptTotal = wpref[32];
    for (int slot = tid; slot < PRE_K; slot += 256) {
        int w = slot >> 6, bo = slot & 63;
        unsigned long long word = skw[w];
        int bit = (int)((word >> bo) & 1ull);
        int kb2 = wpref[w] + __popcll(word & ((1ull << bo) - 1ull));
        int r = bit ? kb2 : keptTotal + (slot - kb2);
        if (r < TOPK) {
            float4 bx = d_cbox[b][slot];
            ((float4*)(out + OFF_BOX))[b * TOPK + r] = bx;
            out[OFF_VAL + b * TOPK + r] = bit ? 1.0f : 0.0f;
            if (bit) {
                float sc = d_cscore[b][slot];
                float sy = bx.z - bx.x, sx = bx.w - bx.y;
                d_hp4[b][r] = make_float4((bx.x + bx.z) * 0.5f, (bx.y + bx.w) * 0.5f,
                                          10.0f / sy, 10.0f / sx);
                d_hlnp[b][r] = logf(sc);
            }
        }
    }
}

// ---------------- K8: heatmap, log-domain max -> single expf per pixel ----------------
__global__ void __launch_bounds__(256) k8_heat(float* __restrict__ out)
{
    int b = blockIdx.y;
    int pix = blockIdx.x * blockDim.x + threadIdx.x;
    __shared__ float4 sh4[TOPK];
    __shared__ float  sl[TOPK];
    int Nk = d_Nk[b];
    for (int i = threadIdx.x; i < Nk; i += blockDim.x) { sh4[i] = d_hp4[b][i]; sl[i] = d_hlnp[b][i]; }
    __syncthreads();
    float fy = (float)(pix / Wd), fx = (float)(pix % Wd);
    float m = -1e30f;
    #pragma unroll 4
    for (int k = 0; k < Nk; k++) {
        float4 h = sh4[k];
        float zy = (fy - h.x) * h.z;
        float zx = (fx - h.y) * h.w;
        float e = fmaf(zy, zy, zx * zx);
        m = fmaxf(m, fmaf(-0.5f, e, sl[k]));
    }
    out[b * HW + pix] = expf(m);   // Nk==0 -> 0
}

// ---------------- launch ----------------
extern "C" void kernel_launch(void* const* d_in, const int* in_sizes, int n_in,
                              void* d_out, int out_size)
{
    const float* mask = (const float*)d_in[0];
    const float* bias = (const float*)d_in[1];
    float* out = (float*)d_out;

    cudaMemcpyAsync(out + OFF_MASK, mask, (size_t)BN * 4 * HW * sizeof(float),
                    cudaMemcpyDeviceToDevice, 0);

    k1_score<<<(BN * (HW/4) + 255) / 256, 256>>>(mask, bias);
    kb1_sort<<<BN, NT1>>>();
    { dim3 g(PRE_K / 8, BN); k5_iou<<<g, 256>>>(); }
    kb2_nms_select<<<BN, 256>>>(out);
    { dim3 g(HW / 256, BN);  k8_heat<<<g, 256>>>(out); }
}